// round 1
// baseline (speedup 1.0000x reference)
#include <cuda_runtime.h>
#include <math.h>

#define BV 16
#define CV 128
#define HV 128
#define WV 128

// Scratch (no allocations allowed): modulated+demodulated weights per (b, o, i, k)
__device__ float g_smax[BV];
__device__ float g_wmax[CV];
__device__ float g_wmod[(size_t)BV * CV * CV * 9];

// ---------------- Kernel 1: per-sample style inf-norm ----------------
__global__ void k_smax(const float* __restrict__ style) {
    int b = blockIdx.x;
    int t = threadIdx.x; // 32 threads
    float m = 0.f;
    for (int i = t; i < CV; i += 32) m = fmaxf(m, fabsf(style[b * CV + i]));
    #pragma unroll
    for (int o = 16; o; o >>= 1) m = fmaxf(m, __shfl_xor_sync(0xffffffffu, m, o));
    if (t == 0) g_smax[b] = m;
}

// ---------------- Kernel 2: per-out-channel weight inf-norm ----------------
__global__ void k_wmax(const float* __restrict__ weight) {
    int o = blockIdx.x;
    int t = threadIdx.x; // 128 threads
    const float* wp = weight + (size_t)o * CV * 9;
    float m = 0.f;
    for (int i = t; i < CV * 9; i += 128) m = fmaxf(m, fabsf(wp[i]));
    __shared__ float red[4];
    #pragma unroll
    for (int off = 16; off; off >>= 1) m = fmaxf(m, __shfl_xor_sync(0xffffffffu, m, off));
    if ((t & 31) == 0) red[t >> 5] = m;
    __syncthreads();
    if (t == 0) g_wmax[o] = fmaxf(fmaxf(red[0], red[1]), fmaxf(red[2], red[3]));
}

// ---------------- Kernel 3: modulate + demodulate ----------------
// wmod[b,o,i,k] = wn[o,i,k] * s[b,i] * coe[b,o]
//   wn = w * (1/sqrt(1152)) / wmax[o];  s = style/smax[b];
//   coe = rsqrt(sum_{i,k} (wn*s)^2 + 1e-8)
__global__ void k_mod(const float* __restrict__ style, const float* __restrict__ weight) {
    int o = blockIdx.x;
    int b = blockIdx.y;
    int i = threadIdx.x; // 128 threads, one input channel each
    float s = style[b * CV + i] / g_smax[b];
    float scale = (1.0f / sqrtf((float)(CV * 9))) / g_wmax[o] * s;
    const float* wp = weight + ((size_t)o * CV + i) * 9;
    float v[9];
    float ss = 0.f;
    #pragma unroll
    for (int k = 0; k < 9; k++) { v[k] = wp[k] * scale; ss += v[k] * v[k]; }
    __shared__ float red[4];
    #pragma unroll
    for (int off = 16; off; off >>= 1) ss += __shfl_xor_sync(0xffffffffu, ss, off);
    if ((i & 31) == 0) red[i >> 5] = ss;
    __syncthreads();
    float coe = rsqrtf(red[0] + red[1] + red[2] + red[3] + 1e-8f);
    float* dst = g_wmod + (((size_t)b * CV + o) * CV + i) * 9;
    #pragma unroll
    for (int k = 0; k < 9; k++) dst[k] = v[k] * coe;
}

// ---------------- Kernel 4: direct conv ----------------
// Block tile: 64 out-channels x (8 rows x 32 cols) pixels, per batch b.
// Thread: 8 oc x 8 rows (col = lane). 256 threads, smem-double-use per ic chunk.
#define ICC 8
__global__ __launch_bounds__(256) void k_conv(const float* __restrict__ x,
                                              float* __restrict__ out) {
    __shared__ float x_s[ICC][10][34];     // halo'd input tile
    __shared__ float w_s[64][ICC * 9];     // weights for 64 oc x ICC ic x 9

    int b = blockIdx.z;
    int ocb = blockIdx.y * 64;
    int tilex = blockIdx.x & 3;            // 4 col tiles of 32
    int tiley = blockIdx.x >> 2;           // 16 row tiles of 8
    int row0 = tiley * 8, col0 = tilex * 32;
    int tid = threadIdx.x;
    int to = tid >> 5;                     // 0..7 : oc group
    int tp = tid & 31;                     // 0..31: pixel column

    float acc[8][8];
    #pragma unroll
    for (int c = 0; c < 8; c++)
        #pragma unroll
        for (int r = 0; r < 8; r++) acc[c][r] = 0.f;

    const float* xb = x + (size_t)b * CV * HV * WV;
    const float* wb = g_wmod + ((size_t)b * CV + ocb) * CV * 9;

    for (int ic0 = 0; ic0 < CV; ic0 += ICC) {
        // Load input tile with halo (zero padding at borders)
        for (int idx = tid; idx < ICC * 10 * 34; idx += 256) {
            int ic = idx / 340;
            int rem = idx % 340;
            int rr = rem / 34;
            int cc = rem % 34;
            int gr = row0 - 1 + rr, gc = col0 - 1 + cc;
            float v = 0.f;
            if ((unsigned)gr < HV && (unsigned)gc < WV)
                v = xb[(size_t)(ic0 + ic) * HV * WV + gr * WV + gc];
            x_s[ic][rr][cc] = v;
        }
        // Load weight chunk (coalesced: ic*9+k contiguous per oc)
        for (int idx = tid; idx < 64 * ICC * 9; idx += 256) {
            int oc = idx / (ICC * 9);
            int rem = idx % (ICC * 9);
            w_s[oc][rem] = wb[(size_t)oc * CV * 9 + ic0 * 9 + rem];
        }
        __syncthreads();

        #pragma unroll
        for (int ic = 0; ic < ICC; ic++) {
            #pragma unroll
            for (int ky = 0; ky < 3; ky++) {
                #pragma unroll
                for (int kx = 0; kx < 3; kx++) {
                    float xv[8];
                    #pragma unroll
                    for (int r = 0; r < 8; r++) xv[r] = x_s[ic][r + ky][tp + kx];
                    float wv[8];
                    #pragma unroll
                    for (int c = 0; c < 8; c++) wv[c] = w_s[to * 8 + c][ic * 9 + ky * 3 + kx];
                    #pragma unroll
                    for (int c = 0; c < 8; c++)
                        #pragma unroll
                        for (int r = 0; r < 8; r++)
                            acc[c][r] = fmaf(wv[c], xv[r], acc[c][r]);
                }
            }
        }
        __syncthreads();
    }

    float* ob = out + ((size_t)b * CV + ocb) * HV * WV;
    #pragma unroll
    for (int c = 0; c < 8; c++) {
        int oc = to * 8 + c;
        #pragma unroll
        for (int r = 0; r < 8; r++)
            ob[(size_t)oc * HV * WV + (row0 + r) * WV + col0 + tp] = acc[c][r];
    }
}

extern "C" void kernel_launch(void* const* d_in, const int* in_sizes, int n_in,
                              void* d_out, int out_size) {
    const float* x      = (const float*)d_in[0];  // (16,128,128,128)
    const float* style  = (const float*)d_in[1];  // (16,128)
    const float* weight = (const float*)d_in[2];  // (128,128,3,3)
    float* out = (float*)d_out;                   // (16,128,128,128)

    k_smax<<<16, 32>>>(style);
    k_wmax<<<128, 128>>>(weight);
    k_mod<<<dim3(128, 16), 128>>>(style, weight);
    k_conv<<<dim3(64, 2, 16), 256>>>(x, out);
}

// round 2
// speedup vs baseline: 1.0467x; 1.0467x over previous
#include <cuda_runtime.h>
#include <math.h>

#define BV 16
#define CV 128
#define HV 128
#define WV 128

// Scratch (no allocations allowed)
__device__ float g_smax[BV];
__device__ float g_wmax[CV];
__device__ float g_wmod[(size_t)BV * CV * CV * 9];

// ---------------- Kernel 1: per-sample style inf-norm ----------------
__global__ void k_smax(const float* __restrict__ style) {
    int b = blockIdx.x;
    int t = threadIdx.x; // 32 threads
    float m = 0.f;
    for (int i = t; i < CV; i += 32) m = fmaxf(m, fabsf(style[b * CV + i]));
    #pragma unroll
    for (int o = 16; o; o >>= 1) m = fmaxf(m, __shfl_xor_sync(0xffffffffu, m, o));
    if (t == 0) g_smax[b] = m;
}

// ---------------- Kernel 2: per-out-channel weight inf-norm ----------------
__global__ void k_wmax(const float* __restrict__ weight) {
    int o = blockIdx.x;
    int t = threadIdx.x; // 128 threads
    const float* wp = weight + (size_t)o * CV * 9;
    float m = 0.f;
    for (int i = t; i < CV * 9; i += 128) m = fmaxf(m, fabsf(wp[i]));
    __shared__ float red[4];
    #pragma unroll
    for (int off = 16; off; off >>= 1) m = fmaxf(m, __shfl_xor_sync(0xffffffffu, m, off));
    if ((t & 31) == 0) red[t >> 5] = m;
    __syncthreads();
    if (t == 0) g_wmax[o] = fmaxf(fmaxf(red[0], red[1]), fmaxf(red[2], red[3]));
}

// ---------------- Kernel 3: modulate + demodulate ----------------
__global__ void k_mod(const float* __restrict__ style, const float* __restrict__ weight) {
    int o = blockIdx.x;
    int b = blockIdx.y;
    int i = threadIdx.x; // 128 threads
    float s = style[b * CV + i] / g_smax[b];
    float scale = (1.0f / sqrtf((float)(CV * 9))) / g_wmax[o] * s;
    const float* wp = weight + ((size_t)o * CV + i) * 9;
    float v[9];
    float ss = 0.f;
    #pragma unroll
    for (int k = 0; k < 9; k++) { v[k] = wp[k] * scale; ss += v[k] * v[k]; }
    __shared__ float red[4];
    #pragma unroll
    for (int off = 16; off; off >>= 1) ss += __shfl_xor_sync(0xffffffffu, ss, off);
    if ((i & 31) == 0) red[i >> 5] = ss;
    __syncthreads();
    float coe = rsqrtf(red[0] + red[1] + red[2] + red[3] + 1e-8f);
    float* dst = g_wmod + (((size_t)b * CV + o) * CV + i) * 9;
    #pragma unroll
    for (int k = 0; k < 9; k++) dst[k] = v[k] * coe;
}

// ---------------- f32x2 packed helpers (SASS FFMA2 path) ----------------
__device__ __forceinline__ void ffma2(unsigned long long& d,
                                      unsigned long long a,
                                      unsigned long long b) {
    asm("fma.rn.f32x2 %0, %1, %2, %0;" : "+l"(d) : "l"(a), "l"(b));
}
__device__ __forceinline__ unsigned long long pack2(float lo, float hi) {
    unsigned long long r;
    asm("mov.b64 %0, {%1, %2};" : "=l"(r) : "f"(lo), "f"(hi));
    return r;
}
__device__ __forceinline__ void unpack2(unsigned long long v, float& lo, float& hi) {
    asm("mov.b64 {%0, %1}, %2;" : "=f"(lo), "=f"(hi) : "l"(v));
}

// ---------------- Kernel 4: direct conv, f32x2 packed ----------------
// Block tile: 64 oc x (8 rows x 64 cols), per batch.
// Thread: 8 oc x 8 rows x 2 cols (one f32x2 per col-pair). 256 threads.
#define ICC 8
#define XW 66   // 64 cols + 2 halo
__global__ __launch_bounds__(256, 1) void k_conv(const float* __restrict__ x,
                                                 float* __restrict__ out) {
    __shared__ float x_s[ICC][10][XW];      // halo'd input tile
    __shared__ float w_s[64][ICC * 9];      // weights: 64 oc x ICC ic x 9

    int b = blockIdx.z;
    int ocb = blockIdx.y * 64;
    int tilex = blockIdx.x & 1;             // 2 col tiles of 64
    int tiley = blockIdx.x >> 1;            // 16 row tiles of 8
    int row0 = tiley * 8, col0 = tilex * 64;
    int tid = threadIdx.x;
    int to = tid >> 5;                      // 0..7 : oc group (warp-uniform)
    int tp = tid & 31;                      // 0..31: col-pair index

    unsigned long long acc[8][8];           // [oc][row], each = 2 cols packed
    #pragma unroll
    for (int c = 0; c < 8; c++)
        #pragma unroll
        for (int r = 0; r < 8; r++) acc[c][r] = 0ull;

    const float* xb = x + (size_t)b * CV * HV * WV;
    const float* wb = g_wmod + ((size_t)b * CV + ocb) * CV * 9;

    for (int ic0 = 0; ic0 < CV; ic0 += ICC) {
        // Load input tile with halo (zero padding at borders)
        for (int idx = tid; idx < ICC * 10 * XW; idx += 256) {
            int ic = idx / (10 * XW);
            int rem = idx % (10 * XW);
            int rr = rem / XW;
            int cc = rem % XW;
            int gr = row0 - 1 + rr, gc = col0 - 1 + cc;
            float v = 0.f;
            if ((unsigned)gr < HV && (unsigned)gc < WV)
                v = xb[(size_t)(ic0 + ic) * HV * WV + gr * WV + gc];
            x_s[ic][rr][cc] = v;
        }
        // Load weight chunk
        for (int idx = tid; idx < 64 * ICC * 9; idx += 256) {
            int oc = idx / (ICC * 9);
            int rem = idx % (ICC * 9);
            w_s[oc][rem] = wb[(size_t)oc * CV * 9 + ic0 * 9 + rem];
        }
        __syncthreads();

        #pragma unroll
        for (int ic = 0; ic < ICC; ic++) {
            #pragma unroll
            for (int ky = 0; ky < 3; ky++) {
                // Two aligned 8B loads per row: cols [2tp,2tp+1], [2tp+2,2tp+3]
                unsigned long long A[8], B[8];
                #pragma unroll
                for (int r = 0; r < 8; r++) {
                    A[r] = *reinterpret_cast<const unsigned long long*>(&x_s[ic][r + ky][2 * tp]);
                    B[r] = *reinterpret_cast<const unsigned long long*>(&x_s[ic][r + ky][2 * tp + 2]);
                }
                // kx = 0
                {
                    #pragma unroll
                    for (int c = 0; c < 8; c++) {
                        float w = w_s[to * 8 + c][ic * 9 + ky * 3 + 0];
                        unsigned long long w2 = pack2(w, w);
                        #pragma unroll
                        for (int r = 0; r < 8; r++) ffma2(acc[c][r], A[r], w2);
                    }
                }
                // kx = 1: operand = {A.hi, B.lo}
                {
                    unsigned long long V[8];
                    #pragma unroll
                    for (int r = 0; r < 8; r++) {
                        float alo, ahi, blo, bhi;
                        unpack2(A[r], alo, ahi);
                        unpack2(B[r], blo, bhi);
                        V[r] = pack2(ahi, blo);
                    }
                    #pragma unroll
                    for (int c = 0; c < 8; c++) {
                        float w = w_s[to * 8 + c][ic * 9 + ky * 3 + 1];
                        unsigned long long w2 = pack2(w, w);
                        #pragma unroll
                        for (int r = 0; r < 8; r++) ffma2(acc[c][r], V[r], w2);
                    }
                }
                // kx = 2
                {
                    #pragma unroll
                    for (int c = 0; c < 8; c++) {
                        float w = w_s[to * 8 + c][ic * 9 + ky * 3 + 2];
                        unsigned long long w2 = pack2(w, w);
                        #pragma unroll
                        for (int r = 0; r < 8; r++) ffma2(acc[c][r], B[r], w2);
                    }
                }
            }
        }
        __syncthreads();
    }

    float* ob = out + ((size_t)b * CV + ocb) * HV * WV;
    #pragma unroll
    for (int c = 0; c < 8; c++) {
        int oc = to * 8 + c;
        #pragma unroll
        for (int r = 0; r < 8; r++) {
            *reinterpret_cast<unsigned long long*>(
                &ob[(size_t)oc * HV * WV + (row0 + r) * WV + col0 + 2 * tp]) = acc[c][r];
        }
    }
}

extern "C" void kernel_launch(void* const* d_in, const int* in_sizes, int n_in,
                              void* d_out, int out_size) {
    const float* x      = (const float*)d_in[0];  // (16,128,128,128)
    const float* style  = (const float*)d_in[1];  // (16,128)
    const float* weight = (const float*)d_in[2];  // (128,128,3,3)
    float* out = (float*)d_out;                   // (16,128,128,128)

    k_smax<<<16, 32>>>(style);
    k_wmax<<<128, 128>>>(weight);
    k_mod<<<dim3(128, 16), 128>>>(style, weight);
    k_conv<<<dim3(32, 2, 16), 256>>>(x, out);
}

// round 5
// speedup vs baseline: 1.6666x; 1.5922x over previous
#include <cuda_runtime.h>
#include <cuda_bf16.h>
#include <stdint.h>
#include <math.h>

#define BV 16
#define CV 128
#define HV 128
#define WV 128

#define A_TILE 32768           // packed A: [kstep 8][mtile 8][lane 32][16B], per split
#define B_TILE 34816           // packed B: [kstep 8][pxi 136][q 4][8B], per split
#define NPX 136                // pixel rows incl. halo (pxi = w+1, w in [-1,134])

__device__ float g_smax[BV];
__device__ float g_wmax[CV];
// Pre-packed A tiles: [b][tap 0..8][split hi/lo], each 32KB, hi/lo contiguous
__device__ unsigned char g_wa[(size_t)BV * 9 * 2 * A_TILE];

// ---------------- helpers ----------------
__device__ __forceinline__ uint32_t smem_u32(const void* p) {
    uint32_t a;
    asm("{ .reg .u64 t; cvta.to.shared.u64 t, %1; cvt.u32.u64 %0, t; }" : "=r"(a) : "l"(p));
    return a;
}
__device__ __forceinline__ void cp_async16(uint32_t dst, const void* src) {
    asm volatile("cp.async.cg.shared.global [%0], [%1], 16;" :: "r"(dst), "l"(src) : "memory");
}
// A fragment packing (mma.m16n8k16 A frag, row-major M x K)
__device__ __forceinline__ uint32_t addrA(int o, int ic) {
    int kstep = ic >> 4, kk = ic & 15, mt = o >> 4;
    int lane = ((o & 7) << 2) | ((kk & 7) >> 1);
    int reg = ((kk >> 3) << 1) | ((o >> 3) & 1);
    return (uint32_t)(((kstep * 8 + mt) * 32 + lane) * 16 + reg * 4 + (kk & 1) * 2);
}
// B fragment packing: [kstep][pxi][q=tig][word0: k=2q,2q+1][word1: k=2q+8,2q+9]
__device__ __forceinline__ uint32_t addrB(int pxi, int ic) {
    int kstep = ic >> 4, kk = ic & 15;
    int q = (kk & 7) >> 1, word = kk >> 3, half = kk & 1;
    return (uint32_t)(((kstep * NPX + pxi) * 4 + q) * 8 + word * 4 + half * 2);
}

__device__ __forceinline__ void mma_bf16(float* c, const uint32_t* a, const uint32_t* b2) {
    asm volatile(
        "mma.sync.aligned.m16n8k16.row.col.f32.bf16.bf16.f32 "
        "{%0,%1,%2,%3}, {%4,%5,%6,%7}, {%8,%9}, {%0,%1,%2,%3};"
        : "+f"(c[0]), "+f"(c[1]), "+f"(c[2]), "+f"(c[3])
        : "r"(a[0]), "r"(a[1]), "r"(a[2]), "r"(a[3]), "r"(b2[0]), "r"(b2[1]));
}

// ---------------- Kernel 1: per-sample style inf-norm ----------------
__global__ void k_smax(const float* __restrict__ style) {
    int b = blockIdx.x, t = threadIdx.x;
    float m = 0.f;
    for (int i = t; i < CV; i += 32) m = fmaxf(m, fabsf(style[b * CV + i]));
    #pragma unroll
    for (int o = 16; o; o >>= 1) m = fmaxf(m, __shfl_xor_sync(0xffffffffu, m, o));
    if (t == 0) g_smax[b] = m;
}

// ---------------- Kernel 2: per-out-channel weight inf-norm ----------------
__global__ void k_wmax(const float* __restrict__ weight) {
    int o = blockIdx.x, t = threadIdx.x;
    const float* wp = weight + (size_t)o * CV * 9;
    float m = 0.f;
    for (int i = t; i < CV * 9; i += 128) m = fmaxf(m, fabsf(wp[i]));
    __shared__ float red[4];
    #pragma unroll
    for (int off = 16; off; off >>= 1) m = fmaxf(m, __shfl_xor_sync(0xffffffffu, m, off));
    if ((t & 31) == 0) red[t >> 5] = m;
    __syncthreads();
    if (t == 0) g_wmax[o] = fmaxf(fmaxf(red[0], red[1]), fmaxf(red[2], red[3]));
}

// ---------------- Kernel 3: modulate+demodulate -> packed bf16 hi/lo A tiles ----------------
__global__ void k_mod(const float* __restrict__ style, const float* __restrict__ weight) {
    int o = blockIdx.x, b = blockIdx.y, i = threadIdx.x;
    float s = style[b * CV + i] / g_smax[b];
    float scale = (1.0f / sqrtf((float)(CV * 9))) / g_wmax[o] * s;
    const float* wp = weight + ((size_t)o * CV + i) * 9;
    float v[9];
    float ss = 0.f;
    #pragma unroll
    for (int k = 0; k < 9; k++) { v[k] = wp[k] * scale; ss += v[k] * v[k]; }
    __shared__ float red[4];
    #pragma unroll
    for (int off = 16; off; off >>= 1) ss += __shfl_xor_sync(0xffffffffu, ss, off);
    if ((i & 31) == 0) red[i >> 5] = ss;
    __syncthreads();
    float coe = rsqrtf(red[0] + red[1] + red[2] + red[3] + 1e-8f);
    uint32_t off = addrA(o, i);
    #pragma unroll
    for (int k = 0; k < 9; k++) {
        float val = v[k] * coe;
        __nv_bfloat16 hi = __float2bfloat16(val);
        __nv_bfloat16 lo = __float2bfloat16(val - __bfloat162float(hi));
        unsigned char* base = g_wa + ((size_t)(b * 9 + k) * 2) * A_TILE;   // tap index k = ky*3+kx
        *(unsigned short*)(base + off) = __bfloat16_as_ushort(hi);
        *(unsigned short*)(base + A_TILE + off) = __bfloat16_as_ushort(lo);
    }
}

// ---------------- Kernel 4: HMMA implicit-GEMM conv ----------------
// CTA = (h, b). 8 warps = 2(M) x 4(N). Warp: 64 oc x 32 px.
#define DYN_SMEM (2 * 2 * A_TILE + 2 * B_TILE)   // 200704 B
__global__ __launch_bounds__(256, 1) void k_conv(const float* __restrict__ x,
                                                 float* __restrict__ out) {
    extern __shared__ unsigned char sm[];
    unsigned char* Abuf[2] = { sm, sm + 2 * A_TILE };      // each: hi(32K)+lo(32K)
    unsigned char* Bh2 = sm + 4 * A_TILE;
    unsigned char* Bl2 = Bh2 + B_TILE;

    int h = blockIdx.x, b = blockIdx.y;
    int tid = threadIdx.x, wid = tid >> 5, lane = tid & 31;
    int warp_m = wid >> 2, warp_n = wid & 3;

    float c[4][4][4];
    #pragma unroll
    for (int mi = 0; mi < 4; mi++)
        #pragma unroll
        for (int ni = 0; ni < 4; ni++)
            #pragma unroll
            for (int r = 0; r < 4; r++) c[mi][ni][r] = 0.f;

    // valid taps, encoded as tap = ky*3 + kx (matches g_wa tile index)
    int tlist[9], ntap = 0;
    #pragma unroll
    for (int ky = 0; ky < 3; ky++) {
        if ((unsigned)(h + ky - 1) >= HV) continue;
        #pragma unroll
        for (int kx = 0; kx < 3; kx++) tlist[ntap++] = ky * 3 + kx;
    }

    // prefetch A(tap0): 64KB contiguous (hi+lo)
    {
        const unsigned char* src = g_wa + ((size_t)(b * 9 + tlist[0]) * 2) * A_TILE;
        uint32_t d = smem_u32(Abuf[0]);
        for (int i = tid; i < 4096; i += 256) cp_async16(d + i * 16, src + (size_t)i * 16);
        asm volatile("cp.async.commit_group;" ::: "memory");
    }

    int prev_ky = -1;
    for (int ti = 0; ti < ntap; ti++) {
        int ky = tlist[ti] / 3, kx = tlist[ti] % 3;
        __syncthreads();   // all warps done with previous tap's mma (B + A buffer safe)

        if (ky != prev_ky) {
            // stage B row h+ky-1: bf16 hi/lo, fragment-packed
            int hh = h + ky - 1;
            for (int it = tid; it < CV * 34; it += 256) {
                int ic = it / 34, g = it % 34;
                const float* xp = x + ((size_t)(b * CV + ic) * HV + hh) * WV;
                #pragma unroll
                for (int j = 0; j < 4; j++) {
                    int pxi = g * 4 + j;
                    int w = pxi - 1;
                    float f = ((unsigned)w < WV) ? xp[w] : 0.f;
                    __nv_bfloat16 fh = __float2bfloat16(f);
                    __nv_bfloat16 fl = __float2bfloat16(f - __bfloat162float(fh));
                    uint32_t off = addrB(pxi, ic);
                    *(unsigned short*)(Bh2 + off) = __bfloat16_as_ushort(fh);
                    *(unsigned short*)(Bl2 + off) = __bfloat16_as_ushort(fl);
                }
            }
            prev_ky = ky;
        }

        if (ti + 1 < ntap) {
            const unsigned char* src = g_wa + ((size_t)(b * 9 + tlist[ti + 1]) * 2) * A_TILE;
            uint32_t d = smem_u32(Abuf[(ti + 1) & 1]);
            for (int i = tid; i < 4096; i += 256) cp_async16(d + i * 16, src + (size_t)i * 16);
            asm volatile("cp.async.commit_group;" ::: "memory");
            asm volatile("cp.async.wait_group 1;" ::: "memory");
        } else {
            asm volatile("cp.async.wait_group 0;" ::: "memory");
        }
        __syncthreads();   // publish A(ti) + B stage

        // ---- mma: 3 split-products x 8 ksteps x 16 HMMA ----
        const unsigned char* Ab = Abuf[ti & 1];
        #pragma unroll
        for (int p = 0; p < 3; p++) {
            const unsigned char* Ap = Ab + ((p == 2) ? A_TILE : 0);       // HH,HL: hi; LH: lo
            const unsigned char* Bp = (p == 1) ? Bl2 : Bh2;               // HL: lo; else hi
            uint32_t Abase = smem_u32(Ap);
            uint32_t Bbase = smem_u32(Bp);
            #pragma unroll
            for (int ks = 0; ks < 8; ks++) {
                uint32_t bf[4][2];
                int pxr = warp_n * 32 + (lane >> 2) + kx;   // shifted pixel row
                #pragma unroll
                for (int ni = 0; ni < 4; ni++) {
                    uint32_t ba = Bbase + ((ks * NPX + pxr + ni * 8) * 4 + (lane & 3)) * 8;
                    asm volatile("ld.shared.v2.u32 {%0,%1}, [%2];"
                                 : "=r"(bf[ni][0]), "=r"(bf[ni][1]) : "r"(ba));
                }
                #pragma unroll
                for (int mi = 0; mi < 4; mi++) {
                    uint32_t af[4];
                    uint32_t aa = Abase + ((ks * 8 + warp_m * 4 + mi) * 32 + lane) * 16;
                    asm volatile("ld.shared.v4.u32 {%0,%1,%2,%3}, [%4];"
                                 : "=r"(af[0]), "=r"(af[1]), "=r"(af[2]), "=r"(af[3]) : "r"(aa));
                    #pragma unroll
                    for (int ni = 0; ni < 4; ni++) mma_bf16(c[mi][ni], af, bf[ni]);
                }
            }
        }
    }

    // ---- epilogue: C regs -> out, 8B stores ----
    #pragma unroll
    for (int mi = 0; mi < 4; mi++) {
        #pragma unroll
        for (int ni = 0; ni < 4; ni++) {
            int oc = warp_m * 64 + mi * 16 + (lane >> 2);
            int px = warp_n * 32 + ni * 8 + (lane & 3) * 2;
            float* op = out + ((size_t)(b * CV + oc) * HV + h) * WV + px;
            *(float2*)op = make_float2(c[mi][ni][0], c[mi][ni][1]);
            *(float2*)(op + (size_t)8 * HV * WV) = make_float2(c[mi][ni][2], c[mi][ni][3]);
        }
    }
}

extern "C" void kernel_launch(void* const* d_in, const int* in_sizes, int n_in,
                              void* d_out, int out_size) {
    const float* x      = (const float*)d_in[0];  // (16,128,128,128)
    const float* style  = (const float*)d_in[1];  // (16,128)
    const float* weight = (const float*)d_in[2];  // (128,128,3,3)
    float* out = (float*)d_out;                   // (16,128,128,128)

    cudaFuncSetAttribute(k_conv, cudaFuncAttributeMaxDynamicSharedMemorySize, DYN_SMEM);

    k_smax<<<16, 32>>>(style);
    k_wmax<<<128, 128>>>(weight);
    k_mod<<<dim3(128, 16), 128>>>(style, weight);
    k_conv<<<dim3(HV, BV), 256, DYN_SMEM>>>(x, out);
}

// round 6
// speedup vs baseline: 3.4096x; 2.0459x over previous
#include <cuda_runtime.h>
#include <cuda_bf16.h>
#include <stdint.h>
#include <math.h>

#define BV 16
#define CV 128
#define HV 128
#define WV 128

#define A_TILE 32768           // packed A: [kstep 8][mtile 8][lane 32][16B], per split
#define B_TILE 34816           // packed B: [kstep 8][pxi 136][32B], per split
#define NPX 136                // pixel rows incl. halo (pxi = w+1, w in [-1,134])

__device__ float g_smax[BV];
__device__ float g_wmax[CV];
// Pre-packed A tiles: [b][tap 0..8][split hi/lo], each 32KB, hi/lo contiguous
__device__ unsigned char g_wa[(size_t)BV * 9 * 2 * A_TILE];

// ---------------- helpers ----------------
__device__ __forceinline__ uint32_t smem_u32(const void* p) {
    uint32_t a;
    asm("{ .reg .u64 t; cvta.to.shared.u64 t, %1; cvt.u32.u64 %0, t; }" : "=r"(a) : "l"(p));
    return a;
}
__device__ __forceinline__ void cp_async16(uint32_t dst, const void* src) {
    asm volatile("cp.async.cg.shared.global [%0], [%1], 16;" :: "r"(dst), "l"(src) : "memory");
}
// A fragment packing (mma.m16n8k16 A frag, row-major M x K)
__device__ __forceinline__ uint32_t addrA(int o, int ic) {
    int kstep = ic >> 4, kk = ic & 15, mt = o >> 4;
    int lane = ((o & 7) << 2) | ((kk & 7) >> 1);
    int reg = ((kk >> 3) << 1) | ((o >> 3) & 1);
    return (uint32_t)(((kstep * 8 + mt) * 32 + lane) * 16 + reg * 4 + (kk & 1) * 2);
}

__device__ __forceinline__ void mma_bf16(float* c, const uint32_t* a, const uint32_t* b2) {
    asm volatile(
        "mma.sync.aligned.m16n8k16.row.col.f32.bf16.bf16.f32 "
        "{%0,%1,%2,%3}, {%4,%5,%6,%7}, {%8,%9}, {%0,%1,%2,%3};"
        : "+f"(c[0]), "+f"(c[1]), "+f"(c[2]), "+f"(c[3])
        : "r"(a[0]), "r"(a[1]), "r"(a[2]), "r"(a[3]), "r"(b2[0]), "r"(b2[1]));
}

// ---------------- Kernel 1: per-sample style inf-norm ----------------
__global__ void k_smax(const float* __restrict__ style) {
    int b = blockIdx.x, t = threadIdx.x;
    float m = 0.f;
    for (int i = t; i < CV; i += 32) m = fmaxf(m, fabsf(style[b * CV + i]));
    #pragma unroll
    for (int o = 16; o; o >>= 1) m = fmaxf(m, __shfl_xor_sync(0xffffffffu, m, o));
    if (t == 0) g_smax[b] = m;
}

// ---------------- Kernel 2: per-out-channel weight inf-norm ----------------
__global__ void k_wmax(const float* __restrict__ weight) {
    int o = blockIdx.x, t = threadIdx.x;
    const float* wp = weight + (size_t)o * CV * 9;
    float m = 0.f;
    for (int i = t; i < CV * 9; i += 128) m = fmaxf(m, fabsf(wp[i]));
    __shared__ float red[4];
    #pragma unroll
    for (int off = 16; off; off >>= 1) m = fmaxf(m, __shfl_xor_sync(0xffffffffu, m, off));
    if ((t & 31) == 0) red[t >> 5] = m;
    __syncthreads();
    if (t == 0) g_wmax[o] = fmaxf(fmaxf(red[0], red[1]), fmaxf(red[2], red[3]));
}

// ---------------- Kernel 3: modulate+demodulate -> packed bf16 hi/lo A tiles ----------------
__global__ void k_mod(const float* __restrict__ style, const float* __restrict__ weight) {
    int o = blockIdx.x, b = blockIdx.y, i = threadIdx.x;
    float s = style[b * CV + i] / g_smax[b];
    float scale = (1.0f / sqrtf((float)(CV * 9))) / g_wmax[o] * s;
    const float* wp = weight + ((size_t)o * CV + i) * 9;
    float v[9];
    float ss = 0.f;
    #pragma unroll
    for (int k = 0; k < 9; k++) { v[k] = wp[k] * scale; ss += v[k] * v[k]; }
    __shared__ float red[4];
    #pragma unroll
    for (int off = 16; off; off >>= 1) ss += __shfl_xor_sync(0xffffffffu, ss, off);
    if ((i & 31) == 0) red[i >> 5] = ss;
    __syncthreads();
    float coe = rsqrtf(red[0] + red[1] + red[2] + red[3] + 1e-8f);
    uint32_t off = addrA(o, i);
    #pragma unroll
    for (int k = 0; k < 9; k++) {
        float val = v[k] * coe;
        __nv_bfloat16 hi = __float2bfloat16(val);
        __nv_bfloat16 lo = __float2bfloat16(val - __bfloat162float(hi));
        unsigned char* base = g_wa + ((size_t)(b * 9 + k) * 2) * A_TILE;   // tap = ky*3+kx
        *(unsigned short*)(base + off) = __bfloat16_as_ushort(hi);
        *(unsigned short*)(base + A_TILE + off) = __bfloat16_as_ushort(lo);
    }
}

// ---------------- Kernel 4: HMMA implicit-GEMM conv ----------------
// CTA = (h, b). 8 warps = 2(M) x 4(N). Warp: 64 oc x 32 px.
#define DYN_SMEM (2 * 2 * A_TILE + 2 * B_TILE)   // 200704 B
__global__ __launch_bounds__(256, 1) void k_conv(const float* __restrict__ x,
                                                 float* __restrict__ out) {
    extern __shared__ unsigned char sm[];
    unsigned char* Abuf[2] = { sm, sm + 2 * A_TILE };      // each: hi(32K)+lo(32K)
    unsigned char* Bh2 = sm + 4 * A_TILE;
    unsigned char* Bl2 = Bh2 + B_TILE;

    int h = blockIdx.x, b = blockIdx.y;
    int tid = threadIdx.x, wid = tid >> 5, lane = tid & 31;
    int warp_m = wid >> 2, warp_n = wid & 3;

    float c[4][4][4];
    #pragma unroll
    for (int mi = 0; mi < 4; mi++)
        #pragma unroll
        for (int ni = 0; ni < 4; ni++)
            #pragma unroll
            for (int r = 0; r < 4; r++) c[mi][ni][r] = 0.f;

    // valid taps, tap = ky*3 + kx
    int tlist[9], ntap = 0;
    #pragma unroll
    for (int ky = 0; ky < 3; ky++) {
        if ((unsigned)(h + ky - 1) >= HV) continue;
        #pragma unroll
        for (int kx = 0; kx < 3; kx++) tlist[ntap++] = ky * 3 + kx;
    }

    // prefetch A(tap0): 64KB contiguous (hi+lo)
    {
        const unsigned char* src = g_wa + ((size_t)(b * 9 + tlist[0]) * 2) * A_TILE;
        uint32_t d = smem_u32(Abuf[0]);
        for (int i = tid; i < 4096; i += 256) cp_async16(d + i * 16, src + (size_t)i * 16);
        asm volatile("cp.async.commit_group;" ::: "memory");
    }

    int prev_ky = -1;
    for (int ti = 0; ti < ntap; ti++) {
        int ky = tlist[ti] / 3, kx = tlist[ti] % 3;
        __syncthreads();   // all warps done with previous tap's mma (B + A buffer safe)

        if (ky != prev_ky) {
            // stage B row h+ky-1: per (kstep, pxi) a contiguous 32B block:
            // ushort order within block: 0,1,8,9, 2,3,10,11, 4,5,12,13, 6,7,14,15
            int hh = h + ky - 1;
            const float* xrow = x + ((size_t)(b * CV) * HV + hh) * WV;
            for (int it = tid; it < 8 * NPX; it += 256) {
                int ks = it / NPX, pxi = it % NPX;
                int w = pxi - 1;
                bool valid = (unsigned)w < WV;
                const float* xp = xrow + (size_t)(ks * 16) * HV * WV + (valid ? w : 0);
                unsigned short hs[16], ls[16];
                #pragma unroll
                for (int j = 0; j < 16; j++) {
                    float f = valid ? xp[(size_t)j * HV * WV] : 0.f;
                    __nv_bfloat16 fh = __float2bfloat16(f);
                    __nv_bfloat16 fl = __float2bfloat16(f - __bfloat162float(fh));
                    // position of kk=j within the 32B block
                    int pos = (((j & 7) >> 1) << 2) | ((j >> 3) << 1) | (j & 1);
                    hs[pos] = __bfloat16_as_ushort(fh);
                    ls[pos] = __bfloat16_as_ushort(fl);
                }
                uint32_t boff = (uint32_t)(ks * NPX + pxi) * 32;
                *(uint4*)(Bh2 + boff)      = *(uint4*)&hs[0];
                *(uint4*)(Bh2 + boff + 16) = *(uint4*)&hs[8];
                *(uint4*)(Bl2 + boff)      = *(uint4*)&ls[0];
                *(uint4*)(Bl2 + boff + 16) = *(uint4*)&ls[8];
            }
            prev_ky = ky;
        }

        if (ti + 1 < ntap) {
            const unsigned char* src = g_wa + ((size_t)(b * 9 + tlist[ti + 1]) * 2) * A_TILE;
            uint32_t d = smem_u32(Abuf[(ti + 1) & 1]);
            for (int i = tid; i < 4096; i += 256) cp_async16(d + i * 16, src + (size_t)i * 16);
            asm volatile("cp.async.commit_group;" ::: "memory");
            asm volatile("cp.async.wait_group 1;" ::: "memory");
        } else {
            asm volatile("cp.async.wait_group 0;" ::: "memory");
        }
        __syncthreads();   // publish A(ti) + B stage

        // ---- mma: per kstep, load all fragments ONCE, then 3 split products ----
        uint32_t AbaseH = smem_u32(Abuf[ti & 1]);
        uint32_t AbaseL = AbaseH + A_TILE;
        uint32_t BbaseH = smem_u32(Bh2);
        uint32_t BbaseL = smem_u32(Bl2);
        int pxr = warp_n * 32 + (lane >> 2) + kx;   // shifted pixel row
        #pragma unroll
        for (int ks = 0; ks < 8; ks++) {
            uint32_t bh[4][2], bl[4][2];
            #pragma unroll
            for (int ni = 0; ni < 4; ni++) {
                uint32_t bo = (uint32_t)((ks * NPX + pxr + ni * 8) * 4 + (lane & 3)) * 8;
                asm volatile("ld.shared.v2.u32 {%0,%1}, [%2];"
                             : "=r"(bh[ni][0]), "=r"(bh[ni][1]) : "r"(BbaseH + bo));
                asm volatile("ld.shared.v2.u32 {%0,%1}, [%2];"
                             : "=r"(bl[ni][0]), "=r"(bl[ni][1]) : "r"(BbaseL + bo));
            }
            #pragma unroll
            for (int mi = 0; mi < 4; mi++) {
                uint32_t ao = (uint32_t)((ks * 8 + warp_m * 4 + mi) * 32 + lane) * 16;
                uint32_t ah[4], al[4];
                asm volatile("ld.shared.v4.u32 {%0,%1,%2,%3}, [%4];"
                             : "=r"(ah[0]), "=r"(ah[1]), "=r"(ah[2]), "=r"(ah[3]) : "r"(AbaseH + ao));
                asm volatile("ld.shared.v4.u32 {%0,%1,%2,%3}, [%4];"
                             : "=r"(al[0]), "=r"(al[1]), "=r"(al[2]), "=r"(al[3]) : "r"(AbaseL + ao));
                #pragma unroll
                for (int ni = 0; ni < 4; ni++) {
                    mma_bf16(c[mi][ni], ah, bh[ni]);   // HH
                    mma_bf16(c[mi][ni], ah, bl[ni]);   // HL
                    mma_bf16(c[mi][ni], al, bh[ni]);   // LH
                }
            }
        }
    }

    // ---- epilogue: C regs -> out, 8B stores ----
    #pragma unroll
    for (int mi = 0; mi < 4; mi++) {
        #pragma unroll
        for (int ni = 0; ni < 4; ni++) {
            int oc = warp_m * 64 + mi * 16 + (lane >> 2);
            int px = warp_n * 32 + ni * 8 + (lane & 3) * 2;
            float* op = out + ((size_t)(b * CV + oc) * HV + h) * WV + px;
            *(float2*)op = make_float2(c[mi][ni][0], c[mi][ni][1]);
            *(float2*)(op + (size_t)8 * HV * WV) = make_float2(c[mi][ni][2], c[mi][ni][3]);
        }
    }
}

extern "C" void kernel_launch(void* const* d_in, const int* in_sizes, int n_in,
                              void* d_out, int out_size) {
    const float* x      = (const float*)d_in[0];  // (16,128,128,128)
    const float* style  = (const float*)d_in[1];  // (16,128)
    const float* weight = (const float*)d_in[2];  // (128,128,3,3)
    float* out = (float*)d_out;                   // (16,128,128,128)

    cudaFuncSetAttribute(k_conv, cudaFuncAttributeMaxDynamicSharedMemorySize, DYN_SMEM);

    k_smax<<<16, 32>>>(style);
    k_wmax<<<128, 128>>>(weight);
    k_mod<<<dim3(128, 16), 128>>>(style, weight);
    k_conv<<<dim3(HV, BV), 256, DYN_SMEM>>>(x, out);
}

// round 7
// speedup vs baseline: 4.5414x; 1.3319x over previous
#include <cuda_runtime.h>
#include <cuda_bf16.h>
#include <stdint.h>
#include <math.h>

#define BV 16
#define CV 128
#define HV 128
#define WV 128

#define A_TILE 32768           // packed A: [kstep 8][mtile 8][lane 32][16B], per split
#define B_TILE 34816           // packed B: [kstep 8][pxi 136][32B], per split
#define NPX 136                // pixel rows incl. halo (pxi = w+1, w in [-1,134])

__device__ float g_smax[BV];
__device__ float g_wmax[CV];
// Pre-packed A tiles: [b][tap 0..8][split hi/lo], each 32KB, hi/lo contiguous
__device__ unsigned char g_wa[(size_t)BV * 9 * 2 * A_TILE];

// ---------------- helpers ----------------
__device__ __forceinline__ uint32_t smem_u32(const void* p) {
    uint32_t a;
    asm("{ .reg .u64 t; cvta.to.shared.u64 t, %1; cvt.u32.u64 %0, t; }" : "=r"(a) : "l"(p));
    return a;
}
// A fragment packing (mma.m16n8k16 A frag, row-major M x K)
__device__ __forceinline__ uint32_t addrA(int o, int ic) {
    int kstep = ic >> 4, kk = ic & 15, mt = o >> 4;
    int lane = ((o & 7) << 2) | ((kk & 7) >> 1);
    int reg = ((kk >> 3) << 1) | ((o >> 3) & 1);
    return (uint32_t)(((kstep * 8 + mt) * 32 + lane) * 16 + reg * 4 + (kk & 1) * 2);
}

__device__ __forceinline__ void mma_bf16(float* c, const uint32_t* a, const uint32_t* b2) {
    asm volatile(
        "mma.sync.aligned.m16n8k16.row.col.f32.bf16.bf16.f32 "
        "{%0,%1,%2,%3}, {%4,%5,%6,%7}, {%8,%9}, {%0,%1,%2,%3};"
        : "+f"(c[0]), "+f"(c[1]), "+f"(c[2]), "+f"(c[3])
        : "r"(a[0]), "r"(a[1]), "r"(a[2]), "r"(a[3]), "r"(b2[0]), "r"(b2[1]));
}

// ---------------- Kernel 1: per-sample style inf-norm ----------------
__global__ void k_smax(const float* __restrict__ style) {
    int b = blockIdx.x, t = threadIdx.x;
    float m = 0.f;
    for (int i = t; i < CV; i += 32) m = fmaxf(m, fabsf(style[b * CV + i]));
    #pragma unroll
    for (int o = 16; o; o >>= 1) m = fmaxf(m, __shfl_xor_sync(0xffffffffu, m, o));
    if (t == 0) g_smax[b] = m;
}

// ---------------- Kernel 2: per-out-channel weight inf-norm ----------------
__global__ void k_wmax(const float* __restrict__ weight) {
    int o = blockIdx.x, t = threadIdx.x;
    const float* wp = weight + (size_t)o * CV * 9;
    float m = 0.f;
    for (int i = t; i < CV * 9; i += 128) m = fmaxf(m, fabsf(wp[i]));
    __shared__ float red[4];
    #pragma unroll
    for (int off = 16; off; off >>= 1) m = fmaxf(m, __shfl_xor_sync(0xffffffffu, m, off));
    if ((t & 31) == 0) red[t >> 5] = m;
    __syncthreads();
    if (t == 0) g_wmax[o] = fmaxf(fmaxf(red[0], red[1]), fmaxf(red[2], red[3]));
}

// ---------------- Kernel 3: modulate+demodulate -> packed bf16 hi/lo A tiles ----------------
__global__ void k_mod(const float* __restrict__ style, const float* __restrict__ weight) {
    int o = blockIdx.x, b = blockIdx.y, i = threadIdx.x;
    float s = style[b * CV + i] / g_smax[b];
    float scale = (1.0f / sqrtf((float)(CV * 9))) / g_wmax[o] * s;
    const float* wp = weight + ((size_t)o * CV + i) * 9;
    float v[9];
    float ss = 0.f;
    #pragma unroll
    for (int k = 0; k < 9; k++) { v[k] = wp[k] * scale; ss += v[k] * v[k]; }
    __shared__ float red[4];
    #pragma unroll
    for (int off = 16; off; off >>= 1) ss += __shfl_xor_sync(0xffffffffu, ss, off);
    if ((i & 31) == 0) red[i >> 5] = ss;
    __syncthreads();
    float coe = rsqrtf(red[0] + red[1] + red[2] + red[3] + 1e-8f);
    uint32_t off = addrA(o, i);
    #pragma unroll
    for (int k = 0; k < 9; k++) {
        float val = v[k] * coe;
        __nv_bfloat16 hi = __float2bfloat16(val);
        __nv_bfloat16 lo = __float2bfloat16(val - __bfloat162float(hi));
        unsigned char* base = g_wa + ((size_t)(b * 9 + k) * 2) * A_TILE;   // tap = ky*3+kx
        *(unsigned short*)(base + off) = __bfloat16_as_ushort(hi);
        *(unsigned short*)(base + A_TILE + off) = __bfloat16_as_ushort(lo);
    }
}

// ---------------- Kernel 4: HMMA implicit-GEMM conv ----------------
// CTA = (h, b). 8 warps = 2(M) x 4(N). Warp: 64 oc x 32 px.
// A fragments come straight from g_wa via LDG (L1-resident, shared by co-resident CTA).
// Smem holds only B (hi+lo) -> 2 CTAs/SM.
#define DYN_SMEM (2 * B_TILE)   // 69632 B
__global__ __launch_bounds__(256, 2) void k_conv(const float* __restrict__ x,
                                                 float* __restrict__ out) {
    extern __shared__ unsigned char sm[];
    unsigned char* Bh2 = sm;
    unsigned char* Bl2 = sm + B_TILE;

    int h = blockIdx.x, b = blockIdx.y;
    int tid = threadIdx.x, wid = tid >> 5, lane = tid & 31;
    int warp_m = wid >> 2, warp_n = wid & 3;

    float c[4][4][4];
    #pragma unroll
    for (int mi = 0; mi < 4; mi++)
        #pragma unroll
        for (int ni = 0; ni < 4; ni++)
            #pragma unroll
            for (int r = 0; r < 4; r++) c[mi][ni][r] = 0.f;

    uint32_t BbaseH = smem_u32(Bh2);
    uint32_t BbaseL = smem_u32(Bl2);

    for (int ky = 0; ky < 3; ky++) {
        int hh = h + ky - 1;
        if ((unsigned)hh >= HV) continue;

        __syncthreads();   // previous taps done reading B
        // ---- stage B row hh: per (kstep, pxi) one contiguous 32B block
        // ushort order within block: 0,1,8,9, 2,3,10,11, 4,5,12,13, 6,7,14,15
        {
            const float* xrow = x + ((size_t)(b * CV) * HV + hh) * WV;
            for (int it = tid; it < 8 * NPX; it += 256) {
                int ks = it / NPX, pxi = it % NPX;
                int w = pxi - 1;
                bool valid = (unsigned)w < WV;
                const float* xp = xrow + (size_t)(ks * 16) * HV * WV + (valid ? w : 0);
                unsigned short hs[16], ls[16];
                #pragma unroll
                for (int j = 0; j < 16; j++) {
                    float f = valid ? xp[(size_t)j * HV * WV] : 0.f;
                    __nv_bfloat16 fh = __float2bfloat16(f);
                    __nv_bfloat16 fl = __float2bfloat16(f - __bfloat162float(fh));
                    int pos = (((j & 7) >> 1) << 2) | ((j >> 3) << 1) | (j & 1);
                    hs[pos] = __bfloat16_as_ushort(fh);
                    ls[pos] = __bfloat16_as_ushort(fl);
                }
                uint32_t boff = (uint32_t)(ks * NPX + pxi) * 32;
                *(uint4*)(Bh2 + boff)      = *(uint4*)&hs[0];
                *(uint4*)(Bh2 + boff + 16) = *(uint4*)&hs[8];
                *(uint4*)(Bl2 + boff)      = *(uint4*)&ls[0];
                *(uint4*)(Bl2 + boff + 16) = *(uint4*)&ls[8];
            }
        }
        __syncthreads();   // B published

        #pragma unroll
        for (int kx = 0; kx < 3; kx++) {
            const unsigned char* Ah = g_wa + ((size_t)(b * 9 + ky * 3 + kx) * 2) * A_TILE;
            const unsigned char* Al = Ah + A_TILE;
            int pxr = warp_n * 32 + (lane >> 2) + kx;   // shifted pixel row
            #pragma unroll
            for (int ks = 0; ks < 8; ks++) {
                uint32_t bh[4][2], bl[4][2];
                #pragma unroll
                for (int ni = 0; ni < 4; ni++) {
                    uint32_t bo = (uint32_t)((ks * NPX + pxr + ni * 8) * 4 + (lane & 3)) * 8;
                    asm volatile("ld.shared.v2.u32 {%0,%1}, [%2];"
                                 : "=r"(bh[ni][0]), "=r"(bh[ni][1]) : "r"(BbaseH + bo));
                    asm volatile("ld.shared.v2.u32 {%0,%1}, [%2];"
                                 : "=r"(bl[ni][0]), "=r"(bl[ni][1]) : "r"(BbaseL + bo));
                }
                #pragma unroll
                for (int mi = 0; mi < 4; mi++) {
                    uint32_t ao = (uint32_t)((ks * 8 + warp_m * 4 + mi) * 32 + lane) * 16;
                    uint4 ahv = __ldg((const uint4*)(Ah + ao));
                    uint4 alv = __ldg((const uint4*)(Al + ao));
                    uint32_t ah[4] = { ahv.x, ahv.y, ahv.z, ahv.w };
                    uint32_t al[4] = { alv.x, alv.y, alv.z, alv.w };
                    #pragma unroll
                    for (int ni = 0; ni < 4; ni++) {
                        mma_bf16(c[mi][ni], ah, bh[ni]);   // HH
                        mma_bf16(c[mi][ni], ah, bl[ni]);   // HL
                        mma_bf16(c[mi][ni], al, bh[ni]);   // LH
                    }
                }
            }
        }
    }

    // ---- epilogue: C regs -> out, 8B stores ----
    #pragma unroll
    for (int mi = 0; mi < 4; mi++) {
        #pragma unroll
        for (int ni = 0; ni < 4; ni++) {
            int oc = warp_m * 64 + mi * 16 + (lane >> 2);
            int px = warp_n * 32 + ni * 8 + (lane & 3) * 2;
            float* op = out + ((size_t)(b * CV + oc) * HV + h) * WV + px;
            *(float2*)op = make_float2(c[mi][ni][0], c[mi][ni][1]);
            *(float2*)(op + (size_t)8 * HV * WV) = make_float2(c[mi][ni][2], c[mi][ni][3]);
        }
    }
}

extern "C" void kernel_launch(void* const* d_in, const int* in_sizes, int n_in,
                              void* d_out, int out_size) {
    const float* x      = (const float*)d_in[0];  // (16,128,128,128)
    const float* style  = (const float*)d_in[1];  // (16,128)
    const float* weight = (const float*)d_in[2];  // (128,128,3,3)
    float* out = (float*)d_out;                   // (16,128,128,128)

    cudaFuncSetAttribute(k_conv, cudaFuncAttributeMaxDynamicSharedMemorySize, DYN_SMEM);

    k_smax<<<16, 32>>>(style);
    k_wmax<<<128, 128>>>(weight);
    k_mod<<<dim3(128, 16), 128>>>(style, weight);
    k_conv<<<dim3(HV, BV), 256, DYN_SMEM>>>(x, out);
}